// round 15
// baseline (speedup 1.0000x reference)
#include <cuda_runtime.h>
#include <cuda_fp16.h>
#include <math.h>
#include <stdint.h>

// Shapes (fixed by dataset)
#define M_DIM 32768
#define K_DIM 1024
#define N_DIM 3072
#define H_DIM 1024
#define T_DIM 2048
#define B_DIM 16

#define BM 128
#define BN 128
#define BK 64                // fp16 elems per chunk = 128 bytes
#define NCH 16               // chunks per tile (K=1024 / 64)
#define NSTG 3
#define A_ST (BM * 128)      // 16384 B per stage
#define B_ST (BN * 128)      // 16384 B per stage
#define STG (A_ST + B_ST)    // 32768 B
#define GEMM_SMEM (NSTG * STG)   // 98304 B -> 2 CTAs/SM

#define NTILN (N_DIM / BN)   // 24
#define NTILES (NTILN * (M_DIM / BM))  // 6144

// Scan chunking (proven R10 config)
#define TC 64
#define NCHK (T_DIM / TC)    // 32

// ---------------------------------------------------------------------------
// Static device scratch (cudaMalloc forbidden)
// ---------------------------------------------------------------------------
__device__ __half g_u[(size_t)M_DIM * N_DIM];                        // 201 MB (fp16 u)
__device__ __half g_a1[(size_t)M_DIM * K_DIM];                       // 67 MB  [m][x_hi]
__device__ __half g_b1[(size_t)N_DIM * K_DIM];                       // 6.3 MB [n][W_hi]
__device__ float g_F[NCHK * B_DIM * H_DIM];                          // 2 MB
__device__ float g_C[NCHK * B_DIM * H_DIM];                          // 2 MB
__device__ float g_cin[NCHK * B_DIM * H_DIM];                        // 2 MB

// ---------------------------------------------------------------------------
// PTX helpers (plain sm_103 features only: cp.async, ldmatrix, mma.sync)
// ---------------------------------------------------------------------------
__device__ __forceinline__ uint32_t smem_u32(const void* p) {
    uint32_t a;
    asm("{ .reg .u64 t; cvta.to.shared.u64 t, %1; cvt.u32.u64 %0, t; }" : "=r"(a) : "l"(p));
    return a;
}
#define CP_ASYNC16(s, g) asm volatile("cp.async.cg.shared.global [%0], [%1], 16;" :: "r"(s), "l"(g) : "memory")
#define CP_COMMIT() asm volatile("cp.async.commit_group;" ::: "memory")
#define CP_WAIT1()  asm volatile("cp.async.wait_group 1;" ::: "memory")

__device__ __forceinline__ void ldsm_x4(uint32_t* r, uint32_t addr) {
    asm volatile("ldmatrix.sync.aligned.m8n8.x4.shared.b16 {%0,%1,%2,%3}, [%4];"
                 : "=r"(r[0]), "=r"(r[1]), "=r"(r[2]), "=r"(r[3]) : "r"(addr));
}
__device__ __forceinline__ void mma_fp16(float* d, const uint32_t* a, uint32_t b0, uint32_t b1) {
    asm volatile("mma.sync.aligned.m16n8k16.row.col.f32.f16.f16.f32 "
                 "{%0,%1,%2,%3},{%4,%5,%6,%7},{%8,%9},{%0,%1,%2,%3};"
                 : "+f"(d[0]), "+f"(d[1]), "+f"(d[2]), "+f"(d[3])
                 : "r"(a[0]), "r"(a[1]), "r"(a[2]), "r"(a[3]), "r"(b0), "r"(b1));
}
#define SWZ128(off) ((off) ^ (((off) >> 3) & 0x70))

// ---------------------------------------------------------------------------
// Conversions: plain fp16 casts (x direct; W^T via smem transpose)
// ---------------------------------------------------------------------------
__global__ __launch_bounds__(256) void convert_x_kernel(const float* __restrict__ x) {
    size_t i = ((size_t)blockIdx.x * 256 + threadIdx.x) * 4;
    float4 v = *reinterpret_cast<const float4*>(x + i);
    const float* vp = &v.x;
    unsigned short hi[4];
#pragma unroll
    for (int j = 0; j < 4; j++) hi[j] = __half_as_ushort(__float2half_rn(vp[j]));
    *reinterpret_cast<uint2*>(g_a1 + i) =
        make_uint2((uint32_t)hi[0] | ((uint32_t)hi[1] << 16),
                   (uint32_t)hi[2] | ((uint32_t)hi[3] << 16));
}

__global__ __launch_bounds__(1024) void convert_w_kernel(const float* __restrict__ W) {
    __shared__ float s[32][33];
    int tx = threadIdx.x, ty = threadIdx.y;
    int n0 = blockIdx.x * 32, k0 = blockIdx.y * 32;
    s[ty][tx] = W[(size_t)(k0 + ty) * N_DIM + n0 + tx];
    __syncthreads();
    float v = s[tx][ty];                 // W[k0+tx][n0+ty]
    g_b1[(size_t)(n0 + ty) * K_DIM + k0 + tx] = __float2half_rn(v);
}

// ---------------------------------------------------------------------------
// Persistent mma.sync fp16 GEMM: CTA 128x128, 256 threads (8 warps, 2x4),
// warp tile 64x32, BK=64, 3-stage cp.async, 2 CTAs/SM.
// Each CTA streams a continuous chunk sequence across its tiles:
// the pipeline never drains; epilogue overlaps next tile's loads.
// ---------------------------------------------------------------------------
__global__ __launch_bounds__(256, 2) void sru_gemm_mma_kernel(const float* __restrict__ bias) {
    extern __shared__ __align__(1024) char dsmem[];
    const uint32_t smem_base = smem_u32(dsmem);

    const int tid = threadIdx.x;
    const int lane = tid & 31;
    const int wid = tid >> 5;
    const int wm = wid & 1;          // 2 warps along M (64 rows each)
    const int wn = wid >> 1;         // 4 warps along N (32 cols each)
    const int bx = blockIdx.x;
    const int G = gridDim.x;

    const char* baseA = reinterpret_cast<const char*>(g_a1);
    const char* baseB = reinterpret_cast<const char*>(g_b1);

    // Per-thread cp.async offsets: 1024 16B-units per tile, 4 per thread
    uint32_t sOo[4], gOo[4];
#pragma unroll
    for (int i = 0; i < 4; i++) {
        int u = i * 256 + tid, row = u >> 3, un = u & 7;
        sOo[i] = SWZ128((uint32_t)(row * 128 + un * 16));
        gOo[i] = (uint32_t)(row * 2048 + un * 16);
    }

    // ldmatrix lane geometry
    const int lr = lane & 15;
    const int lc = lane >> 4;
    const int lq = lane & 7;
    const int brow_off = (lane & 7) + ((lane >> 4) << 3);
    const int cub = (lane >> 3) & 1;

    const int ntiles_mine = (NTILES - bx + G - 1) / G;
    const int totalq = ntiles_mine * NCH;

    float acc[4][4][4];
#pragma unroll
    for (int i = 0; i < 4; i++)
#pragma unroll
        for (int j = 0; j < 4; j++)
#pragma unroll
            for (int q = 0; q < 4; q++) acc[i][j][q] = 0.0f;

    // Prologue: load global chunks 0,1 (stages 0,1)
#pragma unroll
    for (int q = 0; q < NSTG - 1; q++) {
        const int t = bx;                          // q<16 -> first tile
        const char* pA = baseA + ((size_t)(t / NTILN) << 18) + (size_t)(q & 15) * 128;
        const char* pB = baseB + ((size_t)(t % NTILN) << 18) + (size_t)(q & 15) * 128;
        uint32_t st = smem_base + (q % NSTG) * STG;
#pragma unroll
        for (int i = 0; i < 4; i++) CP_ASYNC16(st + sOo[i], pA + gOo[i]);
#pragma unroll
        for (int i = 0; i < 4; i++) CP_ASYNC16(st + A_ST + sOo[i], pB + gOo[i]);
        CP_COMMIT();
    }

#pragma unroll 1
    for (int q = 0; q < totalq; q++) {
        const uint32_t sa = smem_base + (q % NSTG) * STG;
        const uint32_t sb = sa + A_ST;

        CP_WAIT1();            // chunk q arrived (<=1 group pending)
        __syncthreads();       // all warps done with stage (q+2)%NSTG

        // Prefetch global chunk q+2 (crosses tile boundaries seamlessly)
        const int nq = q + NSTG - 1;
        if (nq < totalq) {
            const int t = bx + (nq >> 4) * G;
            const char* pA = baseA + ((size_t)(t / NTILN) << 18) + (size_t)(nq & 15) * 128;
            const char* pB = baseB + ((size_t)(t % NTILN) << 18) + (size_t)(nq & 15) * 128;
            const uint32_t st = smem_base + (nq % NSTG) * STG;
#pragma unroll
            for (int i = 0; i < 4; i++) CP_ASYNC16(st + sOo[i], pA + gOo[i]);
#pragma unroll
            for (int i = 0; i < 4; i++) CP_ASYNC16(st + A_ST + sOo[i], pB + gOo[i]);
        }
        CP_COMMIT();           // unconditional: keeps group accounting aligned

#pragma unroll
        for (int kk = 0; kk < 4; kk++) {
            uint32_t a[4][4], b[2][4];
#pragma unroll
            for (int i = 0; i < 4; i++) {
                int row = wm * 64 + i * 16 + lr;
                ldsm_x4(a[i], sa + row * 128 + (((kk * 2 + lc) ^ lq) << 4));
            }
#pragma unroll
            for (int j = 0; j < 2; j++) {
                int row = wn * 32 + j * 16 + brow_off;
                ldsm_x4(b[j], sb + row * 128 + (((kk * 2 + cub) ^ lq) << 4));
            }
#pragma unroll
            for (int i = 0; i < 4; i++)
#pragma unroll
                for (int j = 0; j < 2; j++) {
                    mma_fp16(acc[i][2 * j],     a[i], b[j][0], b[j][1]);
                    mma_fp16(acc[i][2 * j + 1], a[i], b[j][2], b[j][3]);
                }
        }

        // End of tile: epilogue + acc reset (overlaps in-flight next-tile loads)
        if ((q & 15) == 15) {
            const int t = bx + (q >> 4) * G;
            const int m0 = (t / NTILN) * BM;
            const int n0 = (t % NTILN) * BN;
            const int do_sig = (n0 >= H_DIM);
#pragma unroll
            for (int i = 0; i < 4; i++) {
                const int m = m0 + wm * 64 + i * 16 + (lane >> 2);
                __half* r0 = g_u + (size_t)m * N_DIM;
                __half* r1 = g_u + (size_t)(m + 8) * N_DIM;
#pragma unroll
                for (int tt = 0; tt < 4; tt++) {
                    const int n = n0 + wn * 32 + tt * 8 + (lane & 3) * 2;
                    const float b0 = __ldg(bias + n), b1 = __ldg(bias + n + 1);
                    float v0 = acc[i][tt][0] + b0, v1 = acc[i][tt][1] + b1;
                    float v2 = acc[i][tt][2] + b0, v3 = acc[i][tt][3] + b1;
                    if (do_sig) {
                        v0 = 1.0f / (1.0f + __expf(-v0));
                        v1 = 1.0f / (1.0f + __expf(-v1));
                        v2 = 1.0f / (1.0f + __expf(-v2));
                        v3 = 1.0f / (1.0f + __expf(-v3));
                    }
                    *reinterpret_cast<__half2*>(r0 + n) = __floats2half2_rn(v0, v1);
                    *reinterpret_cast<__half2*>(r1 + n) = __floats2half2_rn(v2, v3);
                }
            }
#pragma unroll
            for (int i = 0; i < 4; i++)
#pragma unroll
                for (int j = 0; j < 4; j++)
#pragma unroll
                    for (int p = 0; p < 4; p++) acc[i][j][p] = 0.0f;
        }
    }
}

// ---------------------------------------------------------------------------
// Chunked scan over fp16 u (two-pass, fp32 state), 2 channels per thread,
// TC=64 chunks (NCHK=32). (Proven best config.)
// ---------------------------------------------------------------------------
__global__ __launch_bounds__(128) void scan_pass1_kernel() {
    const int h2 = blockIdx.x * 128 + threadIdx.x;    // 0..511 channel pairs
    const int b = blockIdx.y;
    const int j = blockIdx.z;

    const __half* up = g_u + ((size_t)b * T_DIM + (size_t)j * TC) * N_DIM + 2 * h2;
    float cx = 0.0f, cy = 0.0f, Fx = 1.0f, Fy = 1.0f;
#pragma unroll 1
    for (int t = 0; t < TC; t += 4) {
        float2 xt[4], ft[4];
#pragma unroll
        for (int i = 0; i < 4; i++) {
            const __half* p = up + (size_t)(t + i) * N_DIM;
            xt[i] = __half22float2(*reinterpret_cast<const __half2*>(p));
            ft[i] = __half22float2(*reinterpret_cast<const __half2*>(p + H_DIM));
        }
#pragma unroll
        for (int i = 0; i < 4; i++) {
            cx = fmaf(ft[i].x, cx, (1.0f - ft[i].x) * xt[i].x);
            cy = fmaf(ft[i].y, cy, (1.0f - ft[i].y) * xt[i].y);
            Fx *= ft[i].x;
            Fy *= ft[i].y;
        }
    }
    const size_t o = ((size_t)j * B_DIM + b) * H_DIM + 2 * h2;
    *reinterpret_cast<float2*>(g_F + o) = make_float2(Fx, Fy);
    *reinterpret_cast<float2*>(g_C + o) = make_float2(cx, cy);
}

__global__ __launch_bounds__(256) void scan_combine_kernel() {
    const int idx = blockIdx.x * 256 + threadIdx.x;   // 0..16383 = b*1024+h
    float c = 0.0f;
#pragma unroll
    for (int j = 0; j < NCHK; j++) {
        const size_t o = (size_t)j * (B_DIM * H_DIM) + idx;
        g_cin[o] = c;
        c = fmaf(g_F[o], c, g_C[o]);
    }
}

__global__ __launch_bounds__(128) void scan_pass2_kernel(float* __restrict__ Hout) {
    const int h2 = blockIdx.x * 128 + threadIdx.x;
    const int b = blockIdx.y;
    const int j = blockIdx.z;

    const __half* up = g_u + ((size_t)b * T_DIM + (size_t)j * TC) * N_DIM + 2 * h2;
    float* op = Hout + ((size_t)b * T_DIM + (size_t)j * TC) * H_DIM + 2 * h2;

    float2 c = *reinterpret_cast<const float2*>(g_cin + ((size_t)j * B_DIM + b) * H_DIM + 2 * h2);
#pragma unroll 1
    for (int t = 0; t < TC; t += 4) {
        float2 xt[4], ft[4], rt[4];
#pragma unroll
        for (int i = 0; i < 4; i++) {
            const __half* p = up + (size_t)(t + i) * N_DIM;
            xt[i] = __half22float2(*reinterpret_cast<const __half2*>(p));
            ft[i] = __half22float2(*reinterpret_cast<const __half2*>(p + H_DIM));
            rt[i] = __half22float2(*reinterpret_cast<const __half2*>(p + 2 * H_DIM));
        }
#pragma unroll
        for (int i = 0; i < 4; i++) {
            c.x = fmaf(ft[i].x, c.x, (1.0f - ft[i].x) * xt[i].x);
            c.y = fmaf(ft[i].y, c.y, (1.0f - ft[i].y) * xt[i].y);
            float hx = fmaf(rt[i].x, tanhf(c.x) - xt[i].x, xt[i].x);
            float hy = fmaf(rt[i].y, tanhf(c.y) - xt[i].y, xt[i].y);
            *reinterpret_cast<float2*>(op + (size_t)(t + i) * H_DIM) = make_float2(hx, hy);
        }
    }
}

// ---------------------------------------------------------------------------
extern "C" void kernel_launch(void* const* d_in, const int* in_sizes, int n_in,
                              void* d_out, int out_size) {
    const float* x = (const float*)d_in[0];
    const float* W = (const float*)d_in[1];
    const float* b = (const float*)d_in[2];
    float* out = (float*)d_out;

    cudaFuncSetAttribute(sru_gemm_mma_kernel,
                         cudaFuncAttributeMaxDynamicSharedMemorySize, GEMM_SMEM);

    int sms = 148;
    cudaDeviceGetAttribute(&sms, cudaDevAttrMultiProcessorCount, 0);
    const int pgrid = 2 * sms;            // persistent: 2 CTAs/SM

    convert_x_kernel<<<(M_DIM * K_DIM / 4) / 256, 256>>>(x);
    convert_w_kernel<<<dim3(N_DIM / 32, K_DIM / 32), dim3(32, 32)>>>(W);

    sru_gemm_mma_kernel<<<pgrid, 256, GEMM_SMEM>>>(b);

    dim3 sgrid(H_DIM / 2 / 128, B_DIM, NCHK); // (4, 16, 32)
    scan_pass1_kernel<<<sgrid, 128>>>();
    scan_combine_kernel<<<(B_DIM * H_DIM) / 256, 256>>>();
    scan_pass2_kernel<<<sgrid, 128>>>(out);
}

// round 16
// speedup vs baseline: 1.0749x; 1.0749x over previous
#include <cuda_runtime.h>
#include <cuda_fp16.h>
#include <math.h>
#include <stdint.h>

// Shapes (fixed by dataset)
#define M_DIM 32768
#define K_DIM 1024
#define N_DIM 3072
#define H_DIM 1024
#define T_DIM 2048
#define B_DIM 16

#define BM 128
#define BN 128
#define BK 64                // fp16 elems per chunk = 128 bytes
#define NCH (K_DIM / BK)     // 16
#define NSTG 3
#define A_ST (BM * 128)      // 16384 B per stage
#define B_ST (BN * 128)      // 16384 B per stage
#define STG (A_ST + B_ST)    // 32768 B
#define GEMM_SMEM (NSTG * STG)   // 98304 B -> 2 CTAs/SM

// Scan chunking (TC=64 -> 2x grid for occupancy)
#define TC 64
#define NCHK (T_DIM / TC)    // 32

// ---------------------------------------------------------------------------
// Static device scratch (cudaMalloc forbidden)
// ---------------------------------------------------------------------------
__device__ __half g_u[(size_t)M_DIM * N_DIM];                        // 201 MB (fp16 u)
__device__ __half g_a1[(size_t)M_DIM * K_DIM];                       // 67 MB  [m][x_hi]
__device__ __half g_b1[(size_t)N_DIM * K_DIM];                       // 6.3 MB [n][W_hi]
__device__ float g_F[NCHK * B_DIM * H_DIM];                          // 2 MB
__device__ float g_C[NCHK * B_DIM * H_DIM];                          // 2 MB
__device__ float g_cin[NCHK * B_DIM * H_DIM];                        // 2 MB

// ---------------------------------------------------------------------------
// PTX helpers (plain sm_103 features only: cp.async, ldmatrix, mma.sync)
// ---------------------------------------------------------------------------
__device__ __forceinline__ uint32_t smem_u32(const void* p) {
    uint32_t a;
    asm("{ .reg .u64 t; cvta.to.shared.u64 t, %1; cvt.u32.u64 %0, t; }" : "=r"(a) : "l"(p));
    return a;
}
#define CP_ASYNC16(s, g) asm volatile("cp.async.cg.shared.global [%0], [%1], 16;" :: "r"(s), "l"(g) : "memory")
#define CP_COMMIT() asm volatile("cp.async.commit_group;" ::: "memory")
#define CP_WAIT1()  asm volatile("cp.async.wait_group 1;" ::: "memory")

__device__ __forceinline__ void ldsm_x4(uint32_t* r, uint32_t addr) {
    asm volatile("ldmatrix.sync.aligned.m8n8.x4.shared.b16 {%0,%1,%2,%3}, [%4];"
                 : "=r"(r[0]), "=r"(r[1]), "=r"(r[2]), "=r"(r[3]) : "r"(addr));
}
__device__ __forceinline__ void mma_fp16(float* d, const uint32_t* a, uint32_t b0, uint32_t b1) {
    asm volatile("mma.sync.aligned.m16n8k16.row.col.f32.f16.f16.f32 "
                 "{%0,%1,%2,%3},{%4,%5,%6,%7},{%8,%9},{%0,%1,%2,%3};"
                 : "+f"(d[0]), "+f"(d[1]), "+f"(d[2]), "+f"(d[3])
                 : "r"(a[0]), "r"(a[1]), "r"(a[2]), "r"(a[3]), "r"(b0), "r"(b1));
}
#define SWZ128(off) ((off) ^ (((off) >> 3) & 0x70))

// ---------------------------------------------------------------------------
// Conversions: plain fp16 casts (x direct; W^T via smem transpose)
// ---------------------------------------------------------------------------
__global__ __launch_bounds__(256) void convert_x_kernel(const float* __restrict__ x) {
    size_t i = ((size_t)blockIdx.x * 256 + threadIdx.x) * 4;
    float4 v = *reinterpret_cast<const float4*>(x + i);
    const float* vp = &v.x;
    unsigned short hi[4];
#pragma unroll
    for (int j = 0; j < 4; j++) hi[j] = __half_as_ushort(__float2half_rn(vp[j]));
    *reinterpret_cast<uint2*>(g_a1 + i) =
        make_uint2((uint32_t)hi[0] | ((uint32_t)hi[1] << 16),
                   (uint32_t)hi[2] | ((uint32_t)hi[3] << 16));
}

__global__ __launch_bounds__(1024) void convert_w_kernel(const float* __restrict__ W) {
    __shared__ float s[32][33];
    int tx = threadIdx.x, ty = threadIdx.y;
    int n0 = blockIdx.x * 32, k0 = blockIdx.y * 32;
    s[ty][tx] = W[(size_t)(k0 + ty) * N_DIM + n0 + tx];
    __syncthreads();
    float v = s[tx][ty];                 // W[k0+tx][n0+ty]
    g_b1[(size_t)(n0 + ty) * K_DIM + k0 + tx] = __float2half_rn(v);
}

// ---------------------------------------------------------------------------
// mma.sync fp16 GEMM: CTA 128x128, 256 threads (8 warps, 2x4 grid),
// warp tile 64x32, BK=64, 3-stage cp.async, 2 CTAs/SM. (Proven best config.)
// Epilogue: +bias, sigmoid on n >= 1024; writes fp16 u.
// ---------------------------------------------------------------------------
__global__ __launch_bounds__(256, 2) void sru_gemm_mma_kernel(const float* __restrict__ bias) {
    extern __shared__ __align__(1024) char dsmem[];
    const uint32_t smem_base = smem_u32(dsmem);

    const int tid = threadIdx.x;
    const int lane = tid & 31;
    const int wid = tid >> 5;
    const int wm = wid & 1;          // 2 warps along M (64 rows each)
    const int wn = wid >> 1;         // 4 warps along N (32 cols each)
    const int m0 = blockIdx.y * BM;
    const int n0 = blockIdx.x * BN;

    const char* gA = reinterpret_cast<const char*>(g_a1) + (size_t)m0 * 2048;   // row pitch 2048 B
    const char* gB = reinterpret_cast<const char*>(g_b1) + (size_t)n0 * 2048;   // row pitch 2048 B

    // Per-thread cp.async offsets: 1024 16B-units per tile, 4 per thread
    uint32_t sOo[4]; size_t gOo[4];
#pragma unroll
    for (int i = 0; i < 4; i++) {
        int u = i * 256 + tid, row = u >> 3, un = u & 7;
        sOo[i] = SWZ128((uint32_t)(row * 128 + un * 16));
        gOo[i] = (size_t)row * 2048 + un * 16;
    }

    // ldmatrix lane geometry
    const int lr = lane & 15;
    const int lc = lane >> 4;
    const int lq = lane & 7;
    const int brow_off = (lane & 7) + ((lane >> 4) << 3);
    const int cub = (lane >> 3) & 1;

    float acc[4][4][4];
#pragma unroll
    for (int i = 0; i < 4; i++)
#pragma unroll
        for (int j = 0; j < 4; j++)
#pragma unroll
            for (int q = 0; q < 4; q++) acc[i][j][q] = 0.0f;

    // Prologue: fill stages 0,1
#pragma unroll
    for (int s = 0; s < NSTG - 1; s++) {
        uint32_t st = smem_base + s * STG;
#pragma unroll
        for (int i = 0; i < 4; i++) CP_ASYNC16(st + sOo[i], gA + gOo[i] + (size_t)s * 128);
#pragma unroll
        for (int i = 0; i < 4; i++) CP_ASYNC16(st + A_ST + sOo[i], gB + gOo[i] + (size_t)s * 128);
        CP_COMMIT();
    }

#pragma unroll 1
    for (int ck = 0; ck < NCH; ck++) {
        const uint32_t sa = smem_base + (ck % NSTG) * STG;
        const uint32_t sb = sa + A_ST;

        CP_WAIT1();            // chunk ck arrived (<=1 group pending)
        __syncthreads();       // all warps done with stage (ck+2)%NSTG

        // Prefetch chunk ck+2 (overlaps with compute of ck)
        const int nck = ck + NSTG - 1;
        if (nck < NCH) {
            const uint32_t st = smem_base + (nck % NSTG) * STG;
#pragma unroll
            for (int i = 0; i < 4; i++) CP_ASYNC16(st + sOo[i], gA + gOo[i] + (size_t)nck * 128);
#pragma unroll
            for (int i = 0; i < 4; i++) CP_ASYNC16(st + A_ST + sOo[i], gB + gOo[i] + (size_t)nck * 128);
        }
        CP_COMMIT();           // unconditional: keeps group accounting aligned

#pragma unroll
        for (int kk = 0; kk < 4; kk++) {
            uint32_t a[4][4], b[2][4];
#pragma unroll
            for (int i = 0; i < 4; i++) {
                int row = wm * 64 + i * 16 + lr;
                ldsm_x4(a[i], sa + row * 128 + (((kk * 2 + lc) ^ lq) << 4));
            }
#pragma unroll
            for (int j = 0; j < 2; j++) {
                int row = wn * 32 + j * 16 + brow_off;
                ldsm_x4(b[j], sb + row * 128 + (((kk * 2 + cub) ^ lq) << 4));
            }
#pragma unroll
            for (int i = 0; i < 4; i++)
#pragma unroll
                for (int j = 0; j < 2; j++) {
                    mma_fp16(acc[i][2 * j],     a[i], b[j][0], b[j][1]);
                    mma_fp16(acc[i][2 * j + 1], a[i], b[j][2], b[j][3]);
                }
        }
    }

    // Epilogue: +bias, sigmoid on n >= 1024, write fp16 u
    const int do_sig = (n0 >= H_DIM);   // thirds 1024-aligned; BN=128 divides
#pragma unroll
    for (int i = 0; i < 4; i++) {
        const int m = m0 + wm * 64 + i * 16 + (lane >> 2);
        __half* r0 = g_u + (size_t)m * N_DIM;
        __half* r1 = g_u + (size_t)(m + 8) * N_DIM;
#pragma unroll
        for (int t = 0; t < 4; t++) {
            const int n = n0 + wn * 32 + t * 8 + (lane & 3) * 2;
            const float b0 = __ldg(bias + n), b1 = __ldg(bias + n + 1);
            float v0 = acc[i][t][0] + b0, v1 = acc[i][t][1] + b1;
            float v2 = acc[i][t][2] + b0, v3 = acc[i][t][3] + b1;
            if (do_sig) {
                v0 = 1.0f / (1.0f + __expf(-v0));
                v1 = 1.0f / (1.0f + __expf(-v1));
                v2 = 1.0f / (1.0f + __expf(-v2));
                v3 = 1.0f / (1.0f + __expf(-v3));
            }
            *reinterpret_cast<__half2*>(r0 + n) = __floats2half2_rn(v0, v1);
            *reinterpret_cast<__half2*>(r1 + n) = __floats2half2_rn(v2, v3);
        }
    }
}

// ---------------------------------------------------------------------------
// Chunked scan over fp16 u (two-pass, fp32 state), 2 channels per thread,
// TC=64 chunks (NCHK=32). (Proven best config.)
// ---------------------------------------------------------------------------
__global__ __launch_bounds__(128) void scan_pass1_kernel() {
    const int h2 = blockIdx.x * 128 + threadIdx.x;    // 0..511 channel pairs
    const int b = blockIdx.y;
    const int j = blockIdx.z;

    const __half* up = g_u + ((size_t)b * T_DIM + (size_t)j * TC) * N_DIM + 2 * h2;
    float cx = 0.0f, cy = 0.0f, Fx = 1.0f, Fy = 1.0f;
#pragma unroll 1
    for (int t = 0; t < TC; t += 4) {
        float2 xt[4], ft[4];
#pragma unroll
        for (int i = 0; i < 4; i++) {
            const __half* p = up + (size_t)(t + i) * N_DIM;
            xt[i] = __half22float2(*reinterpret_cast<const __half2*>(p));
            ft[i] = __half22float2(*reinterpret_cast<const __half2*>(p + H_DIM));
        }
#pragma unroll
        for (int i = 0; i < 4; i++) {
            cx = fmaf(ft[i].x, cx, (1.0f - ft[i].x) * xt[i].x);
            cy = fmaf(ft[i].y, cy, (1.0f - ft[i].y) * xt[i].y);
            Fx *= ft[i].x;
            Fy *= ft[i].y;
        }
    }
    const size_t o = ((size_t)j * B_DIM + b) * H_DIM + 2 * h2;
    *reinterpret_cast<float2*>(g_F + o) = make_float2(Fx, Fy);
    *reinterpret_cast<float2*>(g_C + o) = make_float2(cx, cy);
}

__global__ __launch_bounds__(256) void scan_combine_kernel() {
    const int idx = blockIdx.x * 256 + threadIdx.x;   // 0..16383 = b*1024+h
    float c = 0.0f;
#pragma unroll
    for (int j = 0; j < NCHK; j++) {
        const size_t o = (size_t)j * (B_DIM * H_DIM) + idx;
        g_cin[o] = c;
        c = fmaf(g_F[o], c, g_C[o]);
    }
}

__global__ __launch_bounds__(128) void scan_pass2_kernel(float* __restrict__ Hout) {
    const int h2 = blockIdx.x * 128 + threadIdx.x;
    const int b = blockIdx.y;
    const int j = blockIdx.z;

    const __half* up = g_u + ((size_t)b * T_DIM + (size_t)j * TC) * N_DIM + 2 * h2;
    float* op = Hout + ((size_t)b * T_DIM + (size_t)j * TC) * H_DIM + 2 * h2;

    float2 c = *reinterpret_cast<const float2*>(g_cin + ((size_t)j * B_DIM + b) * H_DIM + 2 * h2);
#pragma unroll 1
    for (int t = 0; t < TC; t += 4) {
        float2 xt[4], ft[4], rt[4];
#pragma unroll
        for (int i = 0; i < 4; i++) {
            const __half* p = up + (size_t)(t + i) * N_DIM;
            xt[i] = __half22float2(*reinterpret_cast<const __half2*>(p));
            ft[i] = __half22float2(*reinterpret_cast<const __half2*>(p + H_DIM));
            rt[i] = __half22float2(*reinterpret_cast<const __half2*>(p + 2 * H_DIM));
        }
#pragma unroll
        for (int i = 0; i < 4; i++) {
            c.x = fmaf(ft[i].x, c.x, (1.0f - ft[i].x) * xt[i].x);
            c.y = fmaf(ft[i].y, c.y, (1.0f - ft[i].y) * xt[i].y);
            float hx = fmaf(rt[i].x, tanhf(c.x) - xt[i].x, xt[i].x);
            float hy = fmaf(rt[i].y, tanhf(c.y) - xt[i].y, xt[i].y);
            *reinterpret_cast<float2*>(op + (size_t)(t + i) * H_DIM) = make_float2(hx, hy);
        }
    }
}

// ---------------------------------------------------------------------------
extern "C" void kernel_launch(void* const* d_in, const int* in_sizes, int n_in,
                              void* d_out, int out_size) {
    const float* x = (const float*)d_in[0];
    const float* W = (const float*)d_in[1];
    const float* b = (const float*)d_in[2];
    float* out = (float*)d_out;

    cudaFuncSetAttribute(sru_gemm_mma_kernel,
                         cudaFuncAttributeMaxDynamicSharedMemorySize, GEMM_SMEM);

    convert_x_kernel<<<(M_DIM * K_DIM / 4) / 256, 256>>>(x);
    convert_w_kernel<<<dim3(N_DIM / 32, K_DIM / 32), dim3(32, 32)>>>(W);

    dim3 ggrid(N_DIM / BN, M_DIM / BM);   // (24, 256)
    sru_gemm_mma_kernel<<<ggrid, 256, GEMM_SMEM>>>(b);

    dim3 sgrid(H_DIM / 2 / 128, B_DIM, NCHK); // (4, 16, 32)
    scan_pass1_kernel<<<sgrid, 128>>>();
    scan_combine_kernel<<<(B_DIM * H_DIM) / 256, 256>>>();
    scan_pass2_kernel<<<sgrid, 128>>>(out);
}

// round 17
// speedup vs baseline: 1.0896x; 1.0138x over previous
#include <cuda_runtime.h>
#include <cuda_fp16.h>
#include <math.h>
#include <stdint.h>

// Shapes (fixed by dataset)
#define M_DIM 32768
#define K_DIM 1024
#define N_DIM 3072
#define H_DIM 1024
#define T_DIM 2048
#define B_DIM 16

#define BM 128
#define BN 128
#define BK 64                // fp16 elems per chunk = 128 bytes
#define NCH (K_DIM / BK)     // 16
#define NSTG 3
#define A_ST (BM * 128)      // 16384 B per stage
#define B_ST (BN * 128)      // 16384 B per stage
#define STG (A_ST + B_ST)    // 32768 B
#define GEMM_SMEM (NSTG * STG)   // 98304 B -> 2 CTAs/SM

// Scan chunking (TC=64 -> 2x grid for occupancy)
#define TC 64
#define NCHK (T_DIM / TC)    // 32

// Merged convert grid split
#define XBLOCKS (M_DIM * K_DIM / 1024)   // 32768 blocks for x cast
#define WBLOCKS ((K_DIM / 32) * (N_DIM / 32))  // 3072 blocks for W transpose

// ---------------------------------------------------------------------------
// Static device scratch (cudaMalloc forbidden)
// ---------------------------------------------------------------------------
__device__ __half g_u[(size_t)M_DIM * N_DIM];                        // 201 MB (fp16 u)
__device__ __half g_a1[(size_t)M_DIM * K_DIM];                       // 67 MB  [m][x_hi]
__device__ __half g_b1[(size_t)N_DIM * K_DIM];                       // 6.3 MB [n][W_hi]
__device__ float g_F[NCHK * B_DIM * H_DIM];                          // 2 MB
__device__ float g_C[NCHK * B_DIM * H_DIM];                          // 2 MB
__device__ float g_cin[NCHK * B_DIM * H_DIM];                        // 2 MB

// ---------------------------------------------------------------------------
// PTX helpers (plain sm_103 features only: cp.async, ldmatrix, mma.sync)
// ---------------------------------------------------------------------------
__device__ __forceinline__ uint32_t smem_u32(const void* p) {
    uint32_t a;
    asm("{ .reg .u64 t; cvta.to.shared.u64 t, %1; cvt.u32.u64 %0, t; }" : "=r"(a) : "l"(p));
    return a;
}
#define CP_ASYNC16(s, g) asm volatile("cp.async.cg.shared.global [%0], [%1], 16;" :: "r"(s), "l"(g) : "memory")
#define CP_COMMIT() asm volatile("cp.async.commit_group;" ::: "memory")
#define CP_WAIT1()  asm volatile("cp.async.wait_group 1;" ::: "memory")

__device__ __forceinline__ void ldsm_x4(uint32_t* r, uint32_t addr) {
    asm volatile("ldmatrix.sync.aligned.m8n8.x4.shared.b16 {%0,%1,%2,%3}, [%4];"
                 : "=r"(r[0]), "=r"(r[1]), "=r"(r[2]), "=r"(r[3]) : "r"(addr));
}
__device__ __forceinline__ void mma_fp16(float* d, const uint32_t* a, uint32_t b0, uint32_t b1) {
    asm volatile("mma.sync.aligned.m16n8k16.row.col.f32.f16.f16.f32 "
                 "{%0,%1,%2,%3},{%4,%5,%6,%7},{%8,%9},{%0,%1,%2,%3};"
                 : "+f"(d[0]), "+f"(d[1]), "+f"(d[2]), "+f"(d[3])
                 : "r"(a[0]), "r"(a[1]), "r"(a[2]), "r"(a[3]), "r"(b0), "r"(b1));
}
#define SWZ128(off) ((off) ^ (((off) >> 3) & 0x70))

// Streaming (evict-first) 4-byte load: u has no L2 reuse, don't pollute.
__device__ __forceinline__ uint32_t ldcs_u32(const void* p) {
    return __ldcs(reinterpret_cast<const uint32_t*>(p));
}
__device__ __forceinline__ float2 ldcs_h2f(const void* p) {
    uint32_t r = __ldcs(reinterpret_cast<const uint32_t*>(p));
    return __half22float2(*reinterpret_cast<const __half2*>(&r));
}

// ---------------------------------------------------------------------------
// Merged conversion: blocks [0, XBLOCKS) cast x -> fp16; blocks
// [XBLOCKS, XBLOCKS+WBLOCKS) transpose+cast a 32x32 W tile -> g_b1.
// ---------------------------------------------------------------------------
__global__ __launch_bounds__(256) void convert_all_kernel(const float* __restrict__ x,
                                                          const float* __restrict__ W) {
    const int bid = blockIdx.x;
    const int tid = threadIdx.x;

    if (bid < XBLOCKS) {
        size_t i = ((size_t)bid * 256 + tid) * 4;
        float4 v = *reinterpret_cast<const float4*>(x + i);
        const float* vp = &v.x;
        unsigned short hi[4];
#pragma unroll
        for (int j = 0; j < 4; j++) hi[j] = __half_as_ushort(__float2half_rn(vp[j]));
        *reinterpret_cast<uint2*>(g_a1 + i) =
            make_uint2((uint32_t)hi[0] | ((uint32_t)hi[1] << 16),
                       (uint32_t)hi[2] | ((uint32_t)hi[3] << 16));
    } else {
        __shared__ float s[32][33];
        const int wt = bid - XBLOCKS;                // 0..3071
        const int n0 = (wt % (N_DIM / 32)) * 32;
        const int k0 = (wt / (N_DIM / 32)) * 32;
        // Load 32x32 tile: thread -> (row = tid/8, cols = (tid%8)*4 ..+3)
        const int lr = tid >> 3, lc = (tid & 7) * 4;
        float4 v = *reinterpret_cast<const float4*>(W + (size_t)(k0 + lr) * N_DIM + n0 + lc);
        s[lr][lc + 0] = v.x; s[lr][lc + 1] = v.y; s[lr][lc + 2] = v.z; s[lr][lc + 3] = v.w;
        __syncthreads();
        // Write transposed: thread -> (n = tid/8, k = (tid%8)*4 ..+3)
        const int tn = tid >> 3, tk = (tid & 7) * 4;
        __half* dst = g_b1 + (size_t)(n0 + tn) * K_DIM + k0 + tk;
        unsigned short h[4];
#pragma unroll
        for (int j = 0; j < 4; j++) h[j] = __half_as_ushort(__float2half_rn(s[tk + j][tn]));
        *reinterpret_cast<uint2*>(dst) =
            make_uint2((uint32_t)h[0] | ((uint32_t)h[1] << 16),
                       (uint32_t)h[2] | ((uint32_t)h[3] << 16));
    }
}

// ---------------------------------------------------------------------------
// mma.sync fp16 GEMM: CTA 128x128, 256 threads (8 warps, 2x4 grid),
// warp tile 64x32, BK=64, 3-stage cp.async, 2 CTAs/SM. (Proven best config.)
// Epilogue: +bias, sigmoid on n >= 1024; writes fp16 u.
// ---------------------------------------------------------------------------
__global__ __launch_bounds__(256, 2) void sru_gemm_mma_kernel(const float* __restrict__ bias) {
    extern __shared__ __align__(1024) char dsmem[];
    const uint32_t smem_base = smem_u32(dsmem);

    const int tid = threadIdx.x;
    const int lane = tid & 31;
    const int wid = tid >> 5;
    const int wm = wid & 1;          // 2 warps along M (64 rows each)
    const int wn = wid >> 1;         // 4 warps along N (32 cols each)
    const int m0 = blockIdx.y * BM;
    const int n0 = blockIdx.x * BN;

    const char* gA = reinterpret_cast<const char*>(g_a1) + (size_t)m0 * 2048;   // row pitch 2048 B
    const char* gB = reinterpret_cast<const char*>(g_b1) + (size_t)n0 * 2048;   // row pitch 2048 B

    // Per-thread cp.async offsets: 1024 16B-units per tile, 4 per thread
    uint32_t sOo[4]; size_t gOo[4];
#pragma unroll
    for (int i = 0; i < 4; i++) {
        int u = i * 256 + tid, row = u >> 3, un = u & 7;
        sOo[i] = SWZ128((uint32_t)(row * 128 + un * 16));
        gOo[i] = (size_t)row * 2048 + un * 16;
    }

    // ldmatrix lane geometry
    const int lr = lane & 15;
    const int lc = lane >> 4;
    const int lq = lane & 7;
    const int brow_off = (lane & 7) + ((lane >> 4) << 3);
    const int cub = (lane >> 3) & 1;

    float acc[4][4][4];
#pragma unroll
    for (int i = 0; i < 4; i++)
#pragma unroll
        for (int j = 0; j < 4; j++)
#pragma unroll
            for (int q = 0; q < 4; q++) acc[i][j][q] = 0.0f;

    // Prologue: fill stages 0,1
#pragma unroll
    for (int s = 0; s < NSTG - 1; s++) {
        uint32_t st = smem_base + s * STG;
#pragma unroll
        for (int i = 0; i < 4; i++) CP_ASYNC16(st + sOo[i], gA + gOo[i] + (size_t)s * 128);
#pragma unroll
        for (int i = 0; i < 4; i++) CP_ASYNC16(st + A_ST + sOo[i], gB + gOo[i] + (size_t)s * 128);
        CP_COMMIT();
    }

#pragma unroll 1
    for (int ck = 0; ck < NCH; ck++) {
        const uint32_t sa = smem_base + (ck % NSTG) * STG;
        const uint32_t sb = sa + A_ST;

        CP_WAIT1();            // chunk ck arrived (<=1 group pending)
        __syncthreads();       // all warps done with stage (ck+2)%NSTG

        // Prefetch chunk ck+2 (overlaps with compute of ck)
        const int nck = ck + NSTG - 1;
        if (nck < NCH) {
            const uint32_t st = smem_base + (nck % NSTG) * STG;
#pragma unroll
            for (int i = 0; i < 4; i++) CP_ASYNC16(st + sOo[i], gA + gOo[i] + (size_t)nck * 128);
#pragma unroll
            for (int i = 0; i < 4; i++) CP_ASYNC16(st + A_ST + sOo[i], gB + gOo[i] + (size_t)nck * 128);
        }
        CP_COMMIT();           // unconditional: keeps group accounting aligned

#pragma unroll
        for (int kk = 0; kk < 4; kk++) {
            uint32_t a[4][4], b[2][4];
#pragma unroll
            for (int i = 0; i < 4; i++) {
                int row = wm * 64 + i * 16 + lr;
                ldsm_x4(a[i], sa + row * 128 + (((kk * 2 + lc) ^ lq) << 4));
            }
#pragma unroll
            for (int j = 0; j < 2; j++) {
                int row = wn * 32 + j * 16 + brow_off;
                ldsm_x4(b[j], sb + row * 128 + (((kk * 2 + cub) ^ lq) << 4));
            }
#pragma unroll
            for (int i = 0; i < 4; i++)
#pragma unroll
                for (int j = 0; j < 2; j++) {
                    mma_fp16(acc[i][2 * j],     a[i], b[j][0], b[j][1]);
                    mma_fp16(acc[i][2 * j + 1], a[i], b[j][2], b[j][3]);
                }
        }
    }

    // Epilogue: +bias, sigmoid on n >= 1024, write fp16 u
    const int do_sig = (n0 >= H_DIM);   // thirds 1024-aligned; BN=128 divides
#pragma unroll
    for (int i = 0; i < 4; i++) {
        const int m = m0 + wm * 64 + i * 16 + (lane >> 2);
        __half* r0 = g_u + (size_t)m * N_DIM;
        __half* r1 = g_u + (size_t)(m + 8) * N_DIM;
#pragma unroll
        for (int t = 0; t < 4; t++) {
            const int n = n0 + wn * 32 + t * 8 + (lane & 3) * 2;
            const float b0 = __ldg(bias + n), b1 = __ldg(bias + n + 1);
            float v0 = acc[i][t][0] + b0, v1 = acc[i][t][1] + b1;
            float v2 = acc[i][t][2] + b0, v3 = acc[i][t][3] + b1;
            if (do_sig) {
                v0 = 1.0f / (1.0f + __expf(-v0));
                v1 = 1.0f / (1.0f + __expf(-v1));
                v2 = 1.0f / (1.0f + __expf(-v2));
                v3 = 1.0f / (1.0f + __expf(-v3));
            }
            *reinterpret_cast<__half2*>(r0 + n) = __floats2half2_rn(v0, v1);
            *reinterpret_cast<__half2*>(r1 + n) = __floats2half2_rn(v2, v3);
        }
    }
}

// ---------------------------------------------------------------------------
// Chunked scan over fp16 u (two-pass, fp32 state), 2 channels per thread,
// TC=64 chunks (NCHK=32). Streaming loads (evict-first) — u has no L2 reuse.
// ---------------------------------------------------------------------------
__global__ __launch_bounds__(128) void scan_pass1_kernel() {
    const int h2 = blockIdx.x * 128 + threadIdx.x;    // 0..511 channel pairs
    const int b = blockIdx.y;
    const int j = blockIdx.z;

    const __half* up = g_u + ((size_t)b * T_DIM + (size_t)j * TC) * N_DIM + 2 * h2;
    float cx = 0.0f, cy = 0.0f, Fx = 1.0f, Fy = 1.0f;
#pragma unroll 1
    for (int t = 0; t < TC; t += 4) {
        float2 xt[4], ft[4];
#pragma unroll
        for (int i = 0; i < 4; i++) {
            const __half* p = up + (size_t)(t + i) * N_DIM;
            xt[i] = ldcs_h2f(p);
            ft[i] = ldcs_h2f(p + H_DIM);
        }
#pragma unroll
        for (int i = 0; i < 4; i++) {
            cx = fmaf(ft[i].x, cx, (1.0f - ft[i].x) * xt[i].x);
            cy = fmaf(ft[i].y, cy, (1.0f - ft[i].y) * xt[i].y);
            Fx *= ft[i].x;
            Fy *= ft[i].y;
        }
    }
    const size_t o = ((size_t)j * B_DIM + b) * H_DIM + 2 * h2;
    *reinterpret_cast<float2*>(g_F + o) = make_float2(Fx, Fy);
    *reinterpret_cast<float2*>(g_C + o) = make_float2(cx, cy);
}

__global__ __launch_bounds__(256) void scan_combine_kernel() {
    const int idx = blockIdx.x * 256 + threadIdx.x;   // 0..16383 = b*1024+h
    float c = 0.0f;
#pragma unroll
    for (int j = 0; j < NCHK; j++) {
        const size_t o = (size_t)j * (B_DIM * H_DIM) + idx;
        g_cin[o] = c;
        c = fmaf(g_F[o], c, g_C[o]);
    }
}

__global__ __launch_bounds__(128) void scan_pass2_kernel(float* __restrict__ Hout) {
    const int h2 = blockIdx.x * 128 + threadIdx.x;
    const int b = blockIdx.y;
    const int j = blockIdx.z;

    const __half* up = g_u + ((size_t)b * T_DIM + (size_t)j * TC) * N_DIM + 2 * h2;
    float* op = Hout + ((size_t)b * T_DIM + (size_t)j * TC) * H_DIM + 2 * h2;

    float2 c = *reinterpret_cast<const float2*>(g_cin + ((size_t)j * B_DIM + b) * H_DIM + 2 * h2);
#pragma unroll 1
    for (int t = 0; t < TC; t += 4) {
        float2 xt[4], ft[4], rt[4];
#pragma unroll
        for (int i = 0; i < 4; i++) {
            const __half* p = up + (size_t)(t + i) * N_DIM;
            xt[i] = ldcs_h2f(p);
            ft[i] = ldcs_h2f(p + H_DIM);
            rt[i] = ldcs_h2f(p + 2 * H_DIM);
        }
#pragma unroll
        for (int i = 0; i < 4; i++) {
            c.x = fmaf(ft[i].x, c.x, (1.0f - ft[i].x) * xt[i].x);
            c.y = fmaf(ft[i].y, c.y, (1.0f - ft[i].y) * xt[i].y);
            float hx = fmaf(rt[i].x, tanhf(c.x) - xt[i].x, xt[i].x);
            float hy = fmaf(rt[i].y, tanhf(c.y) - xt[i].y, xt[i].y);
            *reinterpret_cast<float2*>(op + (size_t)(t + i) * H_DIM) = make_float2(hx, hy);
        }
    }
}

// ---------------------------------------------------------------------------
extern "C" void kernel_launch(void* const* d_in, const int* in_sizes, int n_in,
                              void* d_out, int out_size) {
    const float* x = (const float*)d_in[0];
    const float* W = (const float*)d_in[1];
    const float* b = (const float*)d_in[2];
    float* out = (float*)d_out;

    cudaFuncSetAttribute(sru_gemm_mma_kernel,
                         cudaFuncAttributeMaxDynamicSharedMemorySize, GEMM_SMEM);

    convert_all_kernel<<<XBLOCKS + WBLOCKS, 256>>>(x, W);

    dim3 ggrid(N_DIM / BN, M_DIM / BM);   // (24, 256)
    sru_gemm_mma_kernel<<<ggrid, 256, GEMM_SMEM>>>(b);

    dim3 sgrid(H_DIM / 2 / 128, B_DIM, NCHK); // (4, 16, 32)
    scan_pass1_kernel<<<sgrid, 128>>>();
    scan_combine_kernel<<<(B_DIM * H_DIM) / 256, 256>>>();
    scan_pass2_kernel<<<sgrid, 128>>>(out);
}